// round 4
// baseline (speedup 1.0000x reference)
#include <cuda_runtime.h>
#include <cuda_bf16.h>
#include <cstdint>

#define BATCH 32
#define HID   256
#define VOCAB 10000
#define STEPS 256

// ---------------- recurrence config ----------------
#define NCTA     64
#define DPC      4
#define RTHREADS 256
#define HP       260

// ---------------- scratch (device globals: allocation-free) ----------------
__device__ __nv_bfloat16 g_Ahi[STEPS * BATCH * HID];   // hidden states, bf16 hi
__device__ __nv_bfloat16 g_Alo[STEPS * BATCH * HID];   // bf16 lo (residual)
__device__ __nv_bfloat16 g_Bhi[HID * VOCAB];           // W_hq split
__device__ __nv_bfloat16 g_Blo[HID * VOCAB];
__device__ float    g_hcur[BATCH * HID];
__device__ float    g_rh[BATCH * HID];
__device__ unsigned g_flags[NCTA];                     // per-CTA epoch flags

__global__ void bar_reset_kernel() {
    if (threadIdx.x < NCTA) g_flags[threadIdx.x] = 0u;
}

__global__ void convB_kernel(const float* __restrict__ W) {
    int i = blockIdx.x * 256 + threadIdx.x;
    if (i < HID * VOCAB) {
        float v = W[i];
        __nv_bfloat16 h = __float2bfloat16(v);
        g_Bhi[i] = h;
        g_Blo[i] = __float2bfloat16(v - __bfloat162float(h));
    }
}

// Distributed flag barrier: each CTA release-stores its epoch to its OWN flag
// (no same-address atomic drain); threads 0..63 acquire-spin on one flag each.
__device__ __forceinline__ void grid_barrier(unsigned e) {
    __syncthreads();
    if (threadIdx.x == 0) {
        asm volatile("st.release.gpu.global.u32 [%0], %1;"
                     :: "l"(&g_flags[blockIdx.x]), "r"(e) : "memory");
    }
    if (threadIdx.x < NCTA) {
        unsigned v;
        do {
            asm volatile("ld.acquire.gpu.global.u32 %0, [%1];"
                         : "=r"(v) : "l"(&g_flags[threadIdx.x]) : "memory");
        } while (v < e);
    }
    __syncthreads();
}

// ================= Phase A: persistent GRU recurrence =================
__global__ __launch_bounds__(RTHREADS, 1)
void rnn_kernel(const int* __restrict__ X, const float* __restrict__ H0,
                const float* __restrict__ Wxz, const float* __restrict__ Whz, const float* __restrict__ bz,
                const float* __restrict__ Wxr, const float* __restrict__ Whr, const float* __restrict__ br,
                const float* __restrict__ Wxh, const float* __restrict__ Whh, const float* __restrict__ bh,
                float* __restrict__ outF)
{
    __shared__ float Ws[3 * DPC * HP];
    __shared__ float hbuf[BATCH * HP];
    __shared__ float z_s[BATCH * DPC];
    __shared__ int   x_s[BATCH];

    const int tid  = threadIdx.x;
    const int dim0 = blockIdx.x * DPC;

    for (int i = tid; i < 3 * DPC * HID; i += RTHREADS) {
        int g = i / (DPC * HID);
        int r = i % (DPC * HID);
        int d = r / HID;
        int k = r % HID;
        const float* W = (g == 0) ? Whz : ((g == 1) ? Whr : Whh);
        Ws[(g * DPC + d) * HP + k] = W[k * HID + dim0 + d];
    }

    const int b1 = tid >> 3;
    const int g1 = (tid >> 2) & 1;
    const int d1 = tid & 3;
    const int b2 = tid >> 2;
    const int d2 = tid & 3;

    unsigned epoch = 0;

    #pragma unroll 1
    for (int t = 0; t < STEPS; ++t) {
        const float* hsrc = (t == 0) ? H0 : g_hcur;
        #pragma unroll
        for (int i = 0; i < (BATCH * HID / 4) / RTHREADS; ++i) {
            int f4   = tid + i * RTHREADS;
            int flat = f4 * 4;
            int b    = flat >> 8;
            int k    = flat & (HID - 1);
            float4 v = __ldcg(reinterpret_cast<const float4*>(hsrc + flat));
            *reinterpret_cast<float4*>(&hbuf[b * HP + k]) = v;
        }
        if (tid < BATCH) x_s[tid] = X[tid * STEPS + t];
        __syncthreads();

        // ---- phase 1: z and r ----
        {
            const int dim = dim0 + d1;
            const int xb  = x_s[b1];
            const float* Wx = g1 ? Wxr : Wxz;
            const float* bb = g1 ? br  : bz;
            float xg = Wx[xb * HID + dim] + bb[dim];
            const float* hrow = &hbuf[b1 * HP];
            const float* wrow = &Ws[(g1 * DPC + d1) * HP];
            float acc = 0.f;
            #pragma unroll
            for (int k = 0; k < HID; k += 4) {
                float4 h4 = *reinterpret_cast<const float4*>(hrow + k);
                float4 w4 = *reinterpret_cast<const float4*>(wrow + k);
                acc += h4.x * w4.x + h4.y * w4.y + h4.z * w4.z + h4.w * w4.w;
            }
            float pre = acc + xg;
            float s   = 1.f / (1.f + expf(-pre));
            if (g1 == 0) {
                z_s[b1 * DPC + d1] = s;
            } else {
                float rhv = s * hbuf[b1 * HP + dim];
                __stcg(&g_rh[b1 * HID + dim], rhv);
            }
        }
        grid_barrier(++epoch);

        float hold = 0.f, zval = 0.f, xh = 0.f;
        if (tid < BATCH * DPC) {
            int dim = dim0 + d2;
            hold = hbuf[b2 * HP + dim];
            zval = z_s[b2 * DPC + d2];
            xh   = Wxh[x_s[b2] * HID + dim] + bh[dim];
        }
        __syncthreads();

        #pragma unroll
        for (int i = 0; i < (BATCH * HID / 4) / RTHREADS; ++i) {
            int f4   = tid + i * RTHREADS;
            int flat = f4 * 4;
            int b    = flat >> 8;
            int k    = flat & (HID - 1);
            float4 v = __ldcg(reinterpret_cast<const float4*>(g_rh + flat));
            *reinterpret_cast<float4*>(&hbuf[b * HP + k]) = v;
        }
        __syncthreads();

        // ---- phase 2: h_tilda, h_new ----
        if (tid < BATCH * DPC) {
            int dim = dim0 + d2;
            const float* rrow = &hbuf[b2 * HP];
            const float* wrow = &Ws[(2 * DPC + d2) * HP];
            float acc = 0.f;
            #pragma unroll
            for (int k = 0; k < HID; k += 4) {
                float4 r4 = *reinterpret_cast<const float4*>(rrow + k);
                float4 w4 = *reinterpret_cast<const float4*>(wrow + k);
                acc += r4.x * w4.x + r4.y * w4.y + r4.z * w4.z + r4.w * w4.w;
            }
            float htl  = tanhf(acc + xh);
            float hnew = zval * hold + (1.f - zval) * htl;
            int row = t * BATCH + b2;
            __nv_bfloat16 hb = __float2bfloat16(hnew);
            g_Ahi[row * HID + dim] = hb;
            g_Alo[row * HID + dim] = __float2bfloat16(hnew - __bfloat162float(hb));
            __stcg(&g_hcur[b2 * HID + dim], hnew);
            if (t == STEPS - 1) outF[b2 * HID + dim] = hnew;
        }
        grid_barrier(++epoch);
    }
}

// ================= Phase B: output GEMM (split-bf16 tensor cores) =================
// (byte-identical to round-3 passing version)
#define GBM 128
#define GBN 128
#define GBK 16
#define GNC (HID / GBK)
#define GTHREADS 256

__device__ __forceinline__ uint32_t sptr(const void* p) {
    return (uint32_t)__cvta_generic_to_shared(p);
}
#define CP16(dst, src, sz) \
    asm volatile("cp.async.cg.shared.global [%0], [%1], 16, %2;" :: "r"(dst), "l"(src), "r"(sz))
#define LDSM4(r, addr) \
    asm volatile("ldmatrix.sync.aligned.m8n8.x4.shared.b16 {%0,%1,%2,%3}, [%4];" \
        : "=r"((r)[0]), "=r"((r)[1]), "=r"((r)[2]), "=r"((r)[3]) : "r"(addr))
#define LDSMT2(r, addr) \
    asm volatile("ldmatrix.sync.aligned.m8n8.x2.trans.shared.b16 {%0,%1}, [%2];" \
        : "=r"((r)[0]), "=r"((r)[1]) : "r"(addr))
#define MMA16816(d, a, b) \
    asm volatile("mma.sync.aligned.m16n8k16.row.col.f32.bf16.bf16.f32 " \
        "{%0,%1,%2,%3}, {%4,%5,%6,%7}, {%8,%9}, {%0,%1,%2,%3};" \
        : "+f"((d)[0]), "+f"((d)[1]), "+f"((d)[2]), "+f"((d)[3]) \
        : "r"((a)[0]), "r"((a)[1]), "r"((a)[2]), "r"((a)[3]), "r"((b)[0]), "r"((b)[1]))

__global__ __launch_bounds__(GTHREADS, 1)
void out_gemm(const float* __restrict__ bias, float* __restrict__ C)
{
    __shared__ __align__(16) __nv_bfloat16 sAh[2][GBM * GBK];
    __shared__ __align__(16) __nv_bfloat16 sAl[2][GBM * GBK];
    __shared__ __align__(16) __nv_bfloat16 sBh[2][GBK * GBN];
    __shared__ __align__(16) __nv_bfloat16 sBl[2][GBK * GBN];

    const int tid  = threadIdx.x;
    const int lane = tid & 31;
    const int warp = tid >> 5;
    const int wm   = (warp >> 2) * 64;
    const int wn   = (warp & 3) * 32;
    const int m0   = blockIdx.y * GBM;
    const int n0   = blockIdx.x * GBN;

    float acc[4][4][4];
    #pragma unroll
    for (int i = 0; i < 4; ++i)
        #pragma unroll
        for (int j = 0; j < 4; ++j)
            #pragma unroll
            for (int q = 0; q < 4; ++q) acc[i][j][q] = 0.f;

    auto load_stage = [&](int st, int k0) {
        #pragma unroll
        for (int i = 0; i < 2; ++i) {
            int idx = tid + (i << 8);
            int sel = idx >> 8;
            int r   = idx & 255;
            int m   = r >> 1;
            int ku  = r & 1;
            const __nv_bfloat16* g = (sel ? g_Alo : g_Ahi) + (size_t)(m0 + m) * HID + k0 + ku * 8;
            uint32_t d = sptr(sel ? sAl[st] : sAh[st]) + m * 32 + ((ku ^ ((m >> 2) & 1)) << 4);
            CP16(d, g, 16);
        }
        #pragma unroll
        for (int i = 0; i < 2; ++i) {
            int idx = tid + (i << 8);
            int sel = idx >> 8;
            int r   = idx & 255;
            int k   = r >> 4;
            int nu  = r & 15;
            int col = n0 + nu * 8;
            const __nv_bfloat16* g = (sel ? g_Blo : g_Bhi) + (size_t)(k0 + k) * VOCAB + col;
            uint32_t d = sptr(sel ? sBl[st] : sBh[st]) + k * 256 + ((nu ^ (k & 7)) << 4);
            int sz = (col + 8 <= VOCAB) ? 16 : 0;
            CP16(d, g, sz);
        }
    };

    load_stage(0, 0);
    asm volatile("cp.async.commit_group;");

    const int lrow = lane & 15;
    const int lkb  = (lane >> 4) & 1;

    #pragma unroll 1
    for (int c = 0; c < GNC; ++c) {
        if (c + 1 < GNC) load_stage((c + 1) & 1, (c + 1) * GBK);
        asm volatile("cp.async.commit_group;");
        asm volatile("cp.async.wait_group 1;");
        __syncthreads();

        const int st = c & 1;
        uint32_t ah[4][4], al[4][4], bh[4][2], bl[4][2];
        #pragma unroll
        for (int mt = 0; mt < 4; ++mt) {
            int m = wm + mt * 16 + lrow;
            uint32_t off = m * 32 + ((lkb ^ ((m >> 2) & 1)) << 4);
            LDSM4(ah[mt], sptr(sAh[st]) + off);
            LDSM4(al[mt], sptr(sAl[st]) + off);
        }
        #pragma unroll
        for (int nt = 0; nt < 4; ++nt) {
            int k = lrow;
            int n = wn + nt * 8;
            uint32_t off = k * 256 + (((n >> 3) ^ (k & 7)) << 4);
            LDSMT2(bh[nt], sptr(sBh[st]) + off);
            LDSMT2(bl[nt], sptr(sBl[st]) + off);
        }
        #pragma unroll
        for (int mt = 0; mt < 4; ++mt)
            #pragma unroll
            for (int nt = 0; nt < 4; ++nt) {
                MMA16816(acc[mt][nt], ah[mt], bh[nt]);
                MMA16816(acc[mt][nt], ah[mt], bl[nt]);
                MMA16816(acc[mt][nt], al[mt], bh[nt]);
            }
        __syncthreads();
    }

    #pragma unroll
    for (int nt = 0; nt < 4; ++nt) {
        int cbase = n0 + wn + nt * 8 + 2 * (lane & 3);
        float2 bv = make_float2(0.f, 0.f);
        if (cbase + 1 < VOCAB) bv = *reinterpret_cast<const float2*>(bias + cbase);
        #pragma unroll
        for (int mt = 0; mt < 4; ++mt) {
            int r0 = m0 + wm + mt * 16 + (lane >> 2);
            if (cbase + 1 < VOCAB) {
                float2 v0 = make_float2(acc[mt][nt][0] + bv.x, acc[mt][nt][1] + bv.y);
                float2 v1 = make_float2(acc[mt][nt][2] + bv.x, acc[mt][nt][3] + bv.y);
                *reinterpret_cast<float2*>(C + (size_t)r0 * VOCAB + cbase) = v0;
                *reinterpret_cast<float2*>(C + (size_t)(r0 + 8) * VOCAB + cbase) = v1;
            }
        }
    }
}

// ================= launch =================
extern "C" void kernel_launch(void* const* d_in, const int* in_sizes, int n_in,
                              void* d_out, int out_size) {
    const int*   X   = (const int*)  d_in[0];
    const float* H0  = (const float*)d_in[1];
    const float* Wxz = (const float*)d_in[2];
    const float* Whz = (const float*)d_in[3];
    const float* bz  = (const float*)d_in[4];
    const float* Wxr = (const float*)d_in[5];
    const float* Whr = (const float*)d_in[6];
    const float* br  = (const float*)d_in[7];
    const float* Wxh = (const float*)d_in[8];
    const float* Whh = (const float*)d_in[9];
    const float* bh  = (const float*)d_in[10];
    const float* Whq = (const float*)d_in[11];
    const float* bq  = (const float*)d_in[12];

    float* out  = (float*)d_out;
    float* outF = out + (out_size - BATCH * HID);

    bar_reset_kernel<<<1, 64>>>();
    convB_kernel<<<(HID * VOCAB + 255) / 256, 256>>>(Whq);
    rnn_kernel<<<NCTA, RTHREADS>>>(X, H0, Wxz, Whz, bz, Wxr, Whr, br, Wxh, Whh, bh, outF);
    out_gemm<<<dim3((VOCAB + GBN - 1) / GBN, (STEPS * BATCH) / GBM), GTHREADS>>>(bq, out);
}

// round 5
// speedup vs baseline: 1.4338x; 1.4338x over previous
#include <cuda_runtime.h>
#include <cuda_bf16.h>
#include <cstdint>

#define BATCH 32
#define HID   256
#define VOCAB 10000
#define STEPS 256

// ---------------- recurrence config ----------------
#define NCTA     64
#define DPC      4
#define RTHREADS 256
#define HP       260

// ---------------- scratch (device globals: allocation-free) ----------------
__device__ __nv_bfloat16 g_Ahi[STEPS * BATCH * HID];   // hidden states, bf16 hi
__device__ __nv_bfloat16 g_Alo[STEPS * BATCH * HID];   // bf16 lo (residual)
__device__ __nv_bfloat16 g_Bhi[HID * VOCAB];           // W_hq split
__device__ __nv_bfloat16 g_Blo[HID * VOCAB];
__device__ float    g_hcur[BATCH * HID];
__device__ float    g_rh[BATCH * HID];
__device__ unsigned g_flags[NCTA];                     // per-CTA arrive flags
__device__ unsigned g_release;                         // broadcast word

__global__ void bar_reset_kernel() {
    if (threadIdx.x < NCTA) g_flags[threadIdx.x] = 0u;
    if (threadIdx.x == 0)   g_release = 0u;
}

__global__ void convB_kernel(const float* __restrict__ W) {
    int i = blockIdx.x * 256 + threadIdx.x;
    if (i < HID * VOCAB) {
        float v = W[i];
        __nv_bfloat16 h = __float2bfloat16(v);
        g_Bhi[i] = h;
        g_Blo[i] = __float2bfloat16(v - __bfloat162float(h));
    }
}

__device__ __forceinline__ unsigned ld_acq(const unsigned* p) {
    unsigned v;
    asm volatile("ld.acquire.gpu.global.u32 %0, [%1];" : "=r"(v) : "l"(p) : "memory");
    return v;
}
__device__ __forceinline__ void st_rel(unsigned* p, unsigned v) {
    asm volatile("st.release.gpu.global.u32 [%0], %1;" :: "l"(p), "r"(v) : "memory");
}

// Master-aggregator grid barrier:
//   arrive : each CTA release-stores epoch to its OWN flag (parallel, no drain)
//   gather : CTA 0 only — 64 threads poll the 64 flags
//   release: CTA 0 thread 0 release-stores broadcast word
//   wait   : ONE thread per CTA polls the broadcast word
__device__ __forceinline__ void grid_barrier(unsigned e) {
    __syncthreads();
    if (threadIdx.x == 0) st_rel(&g_flags[blockIdx.x], e);
    if (blockIdx.x == 0) {
        if (threadIdx.x < NCTA)
            while (ld_acq(&g_flags[threadIdx.x]) < e) { }
        __syncthreads();
        if (threadIdx.x == 0) st_rel(&g_release, e);
    }
    if (threadIdx.x == 0)
        while (ld_acq(&g_release) < e) { }
    __syncthreads();
}

// ================= Phase A: persistent GRU recurrence =================
__global__ __launch_bounds__(RTHREADS, 1)
void rnn_kernel(const int* __restrict__ X, const float* __restrict__ H0,
                const float* __restrict__ Wxz, const float* __restrict__ Whz, const float* __restrict__ bz,
                const float* __restrict__ Wxr, const float* __restrict__ Whr, const float* __restrict__ br,
                const float* __restrict__ Wxh, const float* __restrict__ Whh, const float* __restrict__ bh,
                float* __restrict__ outF)
{
    __shared__ float Ws[3 * DPC * HP];
    __shared__ float hbuf[BATCH * HP];
    __shared__ float z_s[BATCH * DPC];
    __shared__ int   x_s[BATCH];

    const int tid  = threadIdx.x;
    const int dim0 = blockIdx.x * DPC;

    for (int i = tid; i < 3 * DPC * HID; i += RTHREADS) {
        int g = i / (DPC * HID);
        int r = i % (DPC * HID);
        int d = r / HID;
        int k = r % HID;
        const float* W = (g == 0) ? Whz : ((g == 1) ? Whr : Whh);
        Ws[(g * DPC + d) * HP + k] = W[k * HID + dim0 + d];
    }

    const int b1 = tid >> 3;
    const int g1 = (tid >> 2) & 1;
    const int d1 = tid & 3;
    const int b2 = tid >> 2;
    const int d2 = tid & 3;

    unsigned epoch = 0;

    #pragma unroll 1
    for (int t = 0; t < STEPS; ++t) {
        // ---- stage h into smem ----
        const float* hsrc = (t == 0) ? H0 : g_hcur;
        #pragma unroll
        for (int i = 0; i < (BATCH * HID / 4) / RTHREADS; ++i) {
            int f4   = tid + i * RTHREADS;
            int flat = f4 * 4;
            int b    = flat >> 8;
            int k    = flat & (HID - 1);
            float4 v = __ldcg(reinterpret_cast<const float4*>(hsrc + flat));
            *reinterpret_cast<float4*>(&hbuf[b * HP + k]) = v;
        }
        if (tid < BATCH) x_s[tid] = X[tid * STEPS + t];
        __syncthreads();

        // ---- prefetch phase-2 inputs that are already available ----
        float hold = 0.f, xh = 0.f;
        if (tid < BATCH * DPC) {
            int dim = dim0 + d2;
            hold = hbuf[b2 * HP + dim];
            xh   = Wxh[x_s[b2] * HID + dim] + bh[dim];   // LDG overlaps phase1 + barrier
        }

        // ---- phase 1: z and r (4 independent partial accumulators) ----
        {
            const int dim = dim0 + d1;
            const int xb  = x_s[b1];
            const float* Wx = g1 ? Wxr : Wxz;
            const float* bb = g1 ? br  : bz;
            float xg = Wx[xb * HID + dim] + bb[dim];
            const float* hrow = &hbuf[b1 * HP];
            const float* wrow = &Ws[(g1 * DPC + d1) * HP];
            float a0 = 0.f, a1 = 0.f, a2 = 0.f, a3 = 0.f;
            #pragma unroll
            for (int k = 0; k < HID; k += 4) {
                float4 h4 = *reinterpret_cast<const float4*>(hrow + k);
                float4 w4 = *reinterpret_cast<const float4*>(wrow + k);
                a0 = fmaf(h4.x, w4.x, a0);
                a1 = fmaf(h4.y, w4.y, a1);
                a2 = fmaf(h4.z, w4.z, a2);
                a3 = fmaf(h4.w, w4.w, a3);
            }
            float pre = ((a0 + a1) + (a2 + a3)) + xg;
            float s   = 1.f / (1.f + expf(-pre));
            if (g1 == 0) {
                z_s[b1 * DPC + d1] = s;
            } else {
                float rhv = s * hbuf[b1 * HP + dim];
                __stcg(&g_rh[b1 * HID + dim], rhv);
            }
        }
        grid_barrier(++epoch);

        float zval = (tid < BATCH * DPC) ? z_s[b2 * DPC + d2] : 0.f;

        // ---- stage r*h over hbuf (all prior hbuf reads done before barrier) ----
        #pragma unroll
        for (int i = 0; i < (BATCH * HID / 4) / RTHREADS; ++i) {
            int f4   = tid + i * RTHREADS;
            int flat = f4 * 4;
            int b    = flat >> 8;
            int k    = flat & (HID - 1);
            float4 v = __ldcg(reinterpret_cast<const float4*>(g_rh + flat));
            *reinterpret_cast<float4*>(&hbuf[b * HP + k]) = v;
        }
        __syncthreads();

        // ---- phase 2: h_tilda, h_new ----
        if (tid < BATCH * DPC) {
            int dim = dim0 + d2;
            const float* rrow = &hbuf[b2 * HP];
            const float* wrow = &Ws[(2 * DPC + d2) * HP];
            float a0 = 0.f, a1 = 0.f, a2 = 0.f, a3 = 0.f;
            #pragma unroll
            for (int k = 0; k < HID; k += 4) {
                float4 r4 = *reinterpret_cast<const float4*>(rrow + k);
                float4 w4 = *reinterpret_cast<const float4*>(wrow + k);
                a0 = fmaf(r4.x, w4.x, a0);
                a1 = fmaf(r4.y, w4.y, a1);
                a2 = fmaf(r4.z, w4.z, a2);
                a3 = fmaf(r4.w, w4.w, a3);
            }
            float htl  = tanhf(((a0 + a1) + (a2 + a3)) + xh);
            float hnew = zval * hold + (1.f - zval) * htl;
            int row = t * BATCH + b2;
            __nv_bfloat16 hb = __float2bfloat16(hnew);
            g_Ahi[row * HID + dim] = hb;
            g_Alo[row * HID + dim] = __float2bfloat16(hnew - __bfloat162float(hb));
            __stcg(&g_hcur[b2 * HID + dim], hnew);
            if (t == STEPS - 1) outF[b2 * HID + dim] = hnew;
        }
        grid_barrier(++epoch);
    }
}

// ================= Phase B: output GEMM (split-bf16 tensor cores) =================
// (byte-identical to round-3 passing version)
#define GBM 128
#define GBN 128
#define GBK 16
#define GNC (HID / GBK)
#define GTHREADS 256

__device__ __forceinline__ uint32_t sptr(const void* p) {
    return (uint32_t)__cvta_generic_to_shared(p);
}
#define CP16(dst, src, sz) \
    asm volatile("cp.async.cg.shared.global [%0], [%1], 16, %2;" :: "r"(dst), "l"(src), "r"(sz))
#define LDSM4(r, addr) \
    asm volatile("ldmatrix.sync.aligned.m8n8.x4.shared.b16 {%0,%1,%2,%3}, [%4];" \
        : "=r"((r)[0]), "=r"((r)[1]), "=r"((r)[2]), "=r"((r)[3]) : "r"(addr))
#define LDSMT2(r, addr) \
    asm volatile("ldmatrix.sync.aligned.m8n8.x2.trans.shared.b16 {%0,%1}, [%2];" \
        : "=r"((r)[0]), "=r"((r)[1]) : "r"(addr))
#define MMA16816(d, a, b) \
    asm volatile("mma.sync.aligned.m16n8k16.row.col.f32.bf16.bf16.f32 " \
        "{%0,%1,%2,%3}, {%4,%5,%6,%7}, {%8,%9}, {%0,%1,%2,%3};" \
        : "+f"((d)[0]), "+f"((d)[1]), "+f"((d)[2]), "+f"((d)[3]) \
        : "r"((a)[0]), "r"((a)[1]), "r"((a)[2]), "r"((a)[3]), "r"((b)[0]), "r"((b)[1]))

__global__ __launch_bounds__(GTHREADS, 1)
void out_gemm(const float* __restrict__ bias, float* __restrict__ C)
{
    __shared__ __align__(16) __nv_bfloat16 sAh[2][GBM * GBK];
    __shared__ __align__(16) __nv_bfloat16 sAl[2][GBM * GBK];
    __shared__ __align__(16) __nv_bfloat16 sBh[2][GBK * GBN];
    __shared__ __align__(16) __nv_bfloat16 sBl[2][GBK * GBN];

    const int tid  = threadIdx.x;
    const int lane = tid & 31;
    const int warp = tid >> 5;
    const int wm   = (warp >> 2) * 64;
    const int wn   = (warp & 3) * 32;
    const int m0   = blockIdx.y * GBM;
    const int n0   = blockIdx.x * GBN;

    float acc[4][4][4];
    #pragma unroll
    for (int i = 0; i < 4; ++i)
        #pragma unroll
        for (int j = 0; j < 4; ++j)
            #pragma unroll
            for (int q = 0; q < 4; ++q) acc[i][j][q] = 0.f;

    auto load_stage = [&](int st, int k0) {
        #pragma unroll
        for (int i = 0; i < 2; ++i) {
            int idx = tid + (i << 8);
            int sel = idx >> 8;
            int r   = idx & 255;
            int m   = r >> 1;
            int ku  = r & 1;
            const __nv_bfloat16* g = (sel ? g_Alo : g_Ahi) + (size_t)(m0 + m) * HID + k0 + ku * 8;
            uint32_t d = sptr(sel ? sAl[st] : sAh[st]) + m * 32 + ((ku ^ ((m >> 2) & 1)) << 4);
            CP16(d, g, 16);
        }
        #pragma unroll
        for (int i = 0; i < 2; ++i) {
            int idx = tid + (i << 8);
            int sel = idx >> 8;
            int r   = idx & 255;
            int k   = r >> 4;
            int nu  = r & 15;
            int col = n0 + nu * 8;
            const __nv_bfloat16* g = (sel ? g_Blo : g_Bhi) + (size_t)(k0 + k) * VOCAB + col;
            uint32_t d = sptr(sel ? sBl[st] : sBh[st]) + k * 256 + ((nu ^ (k & 7)) << 4);
            int sz = (col + 8 <= VOCAB) ? 16 : 0;
            CP16(d, g, sz);
        }
    };

    load_stage(0, 0);
    asm volatile("cp.async.commit_group;");

    const int lrow = lane & 15;
    const int lkb  = (lane >> 4) & 1;

    #pragma unroll 1
    for (int c = 0; c < GNC; ++c) {
        if (c + 1 < GNC) load_stage((c + 1) & 1, (c + 1) * GBK);
        asm volatile("cp.async.commit_group;");
        asm volatile("cp.async.wait_group 1;");
        __syncthreads();

        const int st = c & 1;
        uint32_t ah[4][4], al[4][4], bh[4][2], bl[4][2];
        #pragma unroll
        for (int mt = 0; mt < 4; ++mt) {
            int m = wm + mt * 16 + lrow;
            uint32_t off = m * 32 + ((lkb ^ ((m >> 2) & 1)) << 4);
            LDSM4(ah[mt], sptr(sAh[st]) + off);
            LDSM4(al[mt], sptr(sAl[st]) + off);
        }
        #pragma unroll
        for (int nt = 0; nt < 4; ++nt) {
            int k = lrow;
            int n = wn + nt * 8;
            uint32_t off = k * 256 + (((n >> 3) ^ (k & 7)) << 4);
            LDSMT2(bh[nt], sptr(sBh[st]) + off);
            LDSMT2(bl[nt], sptr(sBl[st]) + off);
        }
        #pragma unroll
        for (int mt = 0; mt < 4; ++mt)
            #pragma unroll
            for (int nt = 0; nt < 4; ++nt) {
                MMA16816(acc[mt][nt], ah[mt], bh[nt]);
                MMA16816(acc[mt][nt], ah[mt], bl[nt]);
                MMA16816(acc[mt][nt], al[mt], bh[nt]);
            }
        __syncthreads();
    }

    #pragma unroll
    for (int nt = 0; nt < 4; ++nt) {
        int cbase = n0 + wn + nt * 8 + 2 * (lane & 3);
        float2 bv = make_float2(0.f, 0.f);
        if (cbase + 1 < VOCAB) bv = *reinterpret_cast<const float2*>(bias + cbase);
        #pragma unroll
        for (int mt = 0; mt < 4; ++mt) {
            int r0 = m0 + wm + mt * 16 + (lane >> 2);
            if (cbase + 1 < VOCAB) {
                float2 v0 = make_float2(acc[mt][nt][0] + bv.x, acc[mt][nt][1] + bv.y);
                float2 v1 = make_float2(acc[mt][nt][2] + bv.x, acc[mt][nt][3] + bv.y);
                *reinterpret_cast<float2*>(C + (size_t)r0 * VOCAB + cbase) = v0;
                *reinterpret_cast<float2*>(C + (size_t)(r0 + 8) * VOCAB + cbase) = v1;
            }
        }
    }
}

// ================= launch =================
extern "C" void kernel_launch(void* const* d_in, const int* in_sizes, int n_in,
                              void* d_out, int out_size) {
    const int*   X   = (const int*)  d_in[0];
    const float* H0  = (const float*)d_in[1];
    const float* Wxz = (const float*)d_in[2];
    const float* Whz = (const float*)d_in[3];
    const float* bz  = (const float*)d_in[4];
    const float* Wxr = (const float*)d_in[5];
    const float* Whr = (const float*)d_in[6];
    const float* br  = (const float*)d_in[7];
    const float* Wxh = (const float*)d_in[8];
    const float* Whh = (const float*)d_in[9];
    const float* bh  = (const float*)d_in[10];
    const float* Whq = (const float*)d_in[11];
    const float* bq  = (const float*)d_in[12];

    float* out  = (float*)d_out;
    float* outF = out + (out_size - BATCH * HID);

    bar_reset_kernel<<<1, 64>>>();
    convB_kernel<<<(HID * VOCAB + 255) / 256, 256>>>(Whq);
    rnn_kernel<<<NCTA, RTHREADS>>>(X, H0, Wxz, Whz, bz, Wxr, Whr, br, Wxh, Whh, bh, outF);
    out_gemm<<<dim3((VOCAB + GBN - 1) / GBN, (STEPS * BATCH) / GBM), GTHREADS>>>(bq, out);
}

// round 6
// speedup vs baseline: 2.5514x; 1.7795x over previous
#include <cuda_runtime.h>
#include <cuda_bf16.h>
#include <cstdint>

#define BATCH 32
#define HID   256
#define VOCAB 10000
#define STEPS 256

// ---------------- recurrence config ----------------
#define CLUSTER 4          // CTAs per cluster (weights split across cluster)
#define BPC     2          // batch elements per cluster
#define DPC     64         // output dims per CTA
#define RTH     128        // threads per CTA: (b, d) = 2 x 64

// ---------------- scratch (device globals: allocation-free) ----------------
__device__ __nv_bfloat16 g_Ahi[STEPS * BATCH * HID];   // hidden states, bf16 hi
__device__ __nv_bfloat16 g_Alo[STEPS * BATCH * HID];   // bf16 lo (residual)
__device__ __nv_bfloat16 g_Bhi[HID * VOCAB];           // W_hq split
__device__ __nv_bfloat16 g_Blo[HID * VOCAB];

__global__ void convB_kernel(const float* __restrict__ W) {
    int i = blockIdx.x * 256 + threadIdx.x;
    if (i < HID * VOCAB) {
        float v = W[i];
        __nv_bfloat16 h = __float2bfloat16(v);
        g_Bhi[i] = h;
        g_Blo[i] = __float2bfloat16(v - __bfloat162float(h));
    }
}

__device__ __forceinline__ uint32_t sptr(const void* p) {
    return (uint32_t)__cvta_generic_to_shared(p);
}

#define FMA2(acc, a, b) \
    asm("fma.rn.f32x2 %0, %1, %2, %0;" : "+l"(acc) : "l"(a), "l"(b))

__device__ __forceinline__ float2 unpack2(unsigned long long v) {
    float2 f;
    asm("mov.b64 {%0, %1}, %2;" : "=f"(f.x), "=f"(f.y) : "l"(v));
    return f;
}

__device__ __forceinline__ void st_cluster_f32(uint32_t laddr, int rank, float v) {
    uint32_t ra;
    asm("mapa.shared::cluster.u32 %0, %1, %2;" : "=r"(ra) : "r"(laddr), "r"(rank));
    asm volatile("st.shared::cluster.f32 [%0], %1;" :: "r"(ra), "f"(v) : "memory");
}

#define CLUSTER_SYNC() do { \
    asm volatile("barrier.cluster.arrive.aligned;" ::: "memory"); \
    asm volatile("barrier.cluster.wait.aligned;"   ::: "memory"); \
} while (0)

// smem layout (dynamic): weight slices interleaved by d for conflict-free LDS.
// Wq[g][kq][d] = float4 of W_h*[4kq..4kq+3][dim0+d]
struct RSmem {
    float4 Wq[3][HID / 4][DPC];   // 3 * 64 * 64 * 16 = 196608 B
    float4 hq[BPC][HID / 4];      // full h vector per local batch (2 KB)
    float4 rhq[BPC][HID / 4];     // full r*h vector per local batch (2 KB)
};

// ================= Phase A: clustered GRU recurrence (no grid barriers) =================
extern __shared__ __align__(16) char rsmem_raw[];

__global__ __launch_bounds__(RTH, 1) __cluster_dims__(CLUSTER, 1, 1)
void rnn_kernel(const int* __restrict__ X, const float* __restrict__ H0,
                const float* __restrict__ Wxz, const float* __restrict__ Whz, const float* __restrict__ bz,
                const float* __restrict__ Wxr, const float* __restrict__ Whr, const float* __restrict__ br,
                const float* __restrict__ Wxh, const float* __restrict__ Whh, const float* __restrict__ bh,
                float* __restrict__ outF)
{
    RSmem* s = reinterpret_cast<RSmem*>(rsmem_raw);
    const int tid  = threadIdx.x;
    const int rank = (int)(blockIdx.x & (CLUSTER - 1));
    const int cid  = (int)(blockIdx.x >> 2);
    const int dim0 = rank * DPC;
    const int b    = tid & 1;          // local batch
    const int d    = tid >> 1;         // local dim
    const int bg   = cid * BPC + b;    // global batch
    const int dim  = dim0 + d;         // global dim owned by this thread

    // ---- load weight slices (one-time), d-interleaved ----
    for (int i = tid; i < 3 * (HID / 4) * DPC; i += RTH) {
        int g  = i / ((HID / 4) * DPC);
        int r  = i % ((HID / 4) * DPC);
        int kq = r / DPC;
        int dd = r % DPC;
        const float* W = (g == 0) ? Whz : ((g == 1) ? Whr : Whh);
        float4 v;
        v.x = W[(kq * 4 + 0) * HID + dim0 + dd];
        v.y = W[(kq * 4 + 1) * HID + dim0 + dd];
        v.z = W[(kq * 4 + 2) * HID + dim0 + dd];
        v.w = W[(kq * 4 + 3) * HID + dim0 + dd];
        s->Wq[g][kq][dd] = v;
    }
    // ---- load initial h (full vector for local batches) ----
    if (tid < BPC * (HID / 4)) {
        int bb = tid >> 6;
        int kq = tid & 63;
        s->hq[bb][kq] = *reinterpret_cast<const float4*>(&H0[(cid * BPC + bb) * HID + kq * 4]);
    }
    const float bzv = bz[dim];
    const float brv = br[dim];
    const float bhv = bh[dim];
    __syncthreads();
    CLUSTER_SYNC();

    const uint32_t rh_addr = sptr(&reinterpret_cast<float*>(s->rhq)[b * HID + dim]);
    const uint32_t h_addr  = sptr(&reinterpret_cast<float*>(s->hq)[b * HID + dim]);

    #pragma unroll 1
    for (int t = 0; t < STEPS; ++t) {
        // ---- gathers for this step (overlap with dot products) ----
        int   xv = X[bg * STEPS + t];
        float xz = Wxz[xv * HID + dim];
        float xr = Wxr[xv * HID + dim];
        float xh = Wxh[xv * HID + dim];
        float hold = reinterpret_cast<const float*>(s->hq)[b * HID + dim];

        // ---- phase A: z and r (packed f32x2 FMA) ----
        unsigned long long az0 = 0ull, az1 = 0ull, ar0 = 0ull, ar1 = 0ull;
        {
            const ulonglong2* wz = reinterpret_cast<const ulonglong2*>(&s->Wq[0][0][d]);
            const ulonglong2* wr = reinterpret_cast<const ulonglong2*>(&s->Wq[1][0][d]);
            const ulonglong2* hp = reinterpret_cast<const ulonglong2*>(&s->hq[b][0]);
            #pragma unroll 16
            for (int kq = 0; kq < HID / 4; ++kq) {
                ulonglong2 h2 = hp[kq];
                ulonglong2 a  = wz[kq * DPC];
                ulonglong2 c  = wr[kq * DPC];
                FMA2(az0, a.x, h2.x); FMA2(az1, a.y, h2.y);
                FMA2(ar0, c.x, h2.x); FMA2(ar1, c.y, h2.y);
            }
        }
        float2 z0 = unpack2(az0), z1 = unpack2(az1);
        float2 r0 = unpack2(ar0), r1 = unpack2(ar1);
        float zpre = ((z0.x + z0.y) + (z1.x + z1.y)) + xz + bzv;
        float rpre = ((r0.x + r0.y) + (r1.x + r1.y)) + xr + brv;
        float zv = 1.f / (1.f + expf(-zpre));
        float rv = 1.f / (1.f + expf(-rpre));
        float rh = rv * hold;

        // broadcast r*h slice to all cluster CTAs (DSMEM)
        #pragma unroll
        for (int rr = 0; rr < CLUSTER; ++rr) st_cluster_f32(rh_addr, rr, rh);
        CLUSTER_SYNC();

        // ---- phase B: h_tilda, h_new ----
        unsigned long long ah0 = 0ull, ah1 = 0ull;
        {
            const ulonglong2* wh = reinterpret_cast<const ulonglong2*>(&s->Wq[2][0][d]);
            const ulonglong2* rp = reinterpret_cast<const ulonglong2*>(&s->rhq[b][0]);
            #pragma unroll 16
            for (int kq = 0; kq < HID / 4; ++kq) {
                ulonglong2 r2 = rp[kq];
                ulonglong2 a  = wh[kq * DPC];
                FMA2(ah0, a.x, r2.x); FMA2(ah1, a.y, r2.y);
            }
        }
        float2 h0 = unpack2(ah0), h1 = unpack2(ah1);
        float htl  = tanhf(((h0.x + h0.y) + (h1.x + h1.y)) + xh + bhv);
        float hnew = zv * hold + (1.f - zv) * htl;

        // broadcast new h slice to all cluster CTAs (DSMEM)
        #pragma unroll
        for (int rr = 0; rr < CLUSTER; ++rr) st_cluster_f32(h_addr, rr, hnew);

        // emit split-bf16 A matrix row for the output GEMM
        int row = t * BATCH + bg;
        __nv_bfloat16 hb = __float2bfloat16(hnew);
        g_Ahi[row * HID + dim] = hb;
        g_Alo[row * HID + dim] = __float2bfloat16(hnew - __bfloat162float(hb));
        if (t == STEPS - 1) outF[bg * HID + dim] = hnew;

        CLUSTER_SYNC();
    }
}

// ================= Phase B: output GEMM (split-bf16 tensor cores) =================
// (byte-identical to round-3 passing version)
#define GBM 128
#define GBN 128
#define GBK 16
#define GNC (HID / GBK)
#define GTHREADS 256

#define CP16(dst, src, sz) \
    asm volatile("cp.async.cg.shared.global [%0], [%1], 16, %2;" :: "r"(dst), "l"(src), "r"(sz))
#define LDSM4(r, addr) \
    asm volatile("ldmatrix.sync.aligned.m8n8.x4.shared.b16 {%0,%1,%2,%3}, [%4];" \
        : "=r"((r)[0]), "=r"((r)[1]), "=r"((r)[2]), "=r"((r)[3]) : "r"(addr))
#define LDSMT2(r, addr) \
    asm volatile("ldmatrix.sync.aligned.m8n8.x2.trans.shared.b16 {%0,%1}, [%2];" \
        : "=r"((r)[0]), "=r"((r)[1]) : "r"(addr))
#define MMA16816(d, a, b) \
    asm volatile("mma.sync.aligned.m16n8k16.row.col.f32.bf16.bf16.f32 " \
        "{%0,%1,%2,%3}, {%4,%5,%6,%7}, {%8,%9}, {%0,%1,%2,%3};" \
        : "+f"((d)[0]), "+f"((d)[1]), "+f"((d)[2]), "+f"((d)[3]) \
        : "r"((a)[0]), "r"((a)[1]), "r"((a)[2]), "r"((a)[3]), "r"((b)[0]), "r"((b)[1]))

__global__ __launch_bounds__(GTHREADS, 1)
void out_gemm(const float* __restrict__ bias, float* __restrict__ C)
{
    __shared__ __align__(16) __nv_bfloat16 sAh[2][GBM * GBK];
    __shared__ __align__(16) __nv_bfloat16 sAl[2][GBM * GBK];
    __shared__ __align__(16) __nv_bfloat16 sBh[2][GBK * GBN];
    __shared__ __align__(16) __nv_bfloat16 sBl[2][GBK * GBN];

    const int tid  = threadIdx.x;
    const int lane = tid & 31;
    const int warp = tid >> 5;
    const int wm   = (warp >> 2) * 64;
    const int wn   = (warp & 3) * 32;
    const int m0   = blockIdx.y * GBM;
    const int n0   = blockIdx.x * GBN;

    float acc[4][4][4];
    #pragma unroll
    for (int i = 0; i < 4; ++i)
        #pragma unroll
        for (int j = 0; j < 4; ++j)
            #pragma unroll
            for (int q = 0; q < 4; ++q) acc[i][j][q] = 0.f;

    auto load_stage = [&](int st, int k0) {
        #pragma unroll
        for (int i = 0; i < 2; ++i) {
            int idx = tid + (i << 8);
            int sel = idx >> 8;
            int r   = idx & 255;
            int m   = r >> 1;
            int ku  = r & 1;
            const __nv_bfloat16* g = (sel ? g_Alo : g_Ahi) + (size_t)(m0 + m) * HID + k0 + ku * 8;
            uint32_t d = sptr(sel ? sAl[st] : sAh[st]) + m * 32 + ((ku ^ ((m >> 2) & 1)) << 4);
            CP16(d, g, 16);
        }
        #pragma unroll
        for (int i = 0; i < 2; ++i) {
            int idx = tid + (i << 8);
            int sel = idx >> 8;
            int r   = idx & 255;
            int k   = r >> 4;
            int nu  = r & 15;
            int col = n0 + nu * 8;
            const __nv_bfloat16* g = (sel ? g_Blo : g_Bhi) + (size_t)(k0 + k) * VOCAB + col;
            uint32_t d = sptr(sel ? sBl[st] : sBh[st]) + k * 256 + ((nu ^ (k & 7)) << 4);
            int sz = (col + 8 <= VOCAB) ? 16 : 0;
            CP16(d, g, sz);
        }
    };

    load_stage(0, 0);
    asm volatile("cp.async.commit_group;");

    const int lrow = lane & 15;
    const int lkb  = (lane >> 4) & 1;

    #pragma unroll 1
    for (int c = 0; c < GNC; ++c) {
        if (c + 1 < GNC) load_stage((c + 1) & 1, (c + 1) * GBK);
        asm volatile("cp.async.commit_group;");
        asm volatile("cp.async.wait_group 1;");
        __syncthreads();

        const int st = c & 1;
        uint32_t ah[4][4], al[4][4], bh[4][2], bl[4][2];
        #pragma unroll
        for (int mt = 0; mt < 4; ++mt) {
            int m = wm + mt * 16 + lrow;
            uint32_t off = m * 32 + ((lkb ^ ((m >> 2) & 1)) << 4);
            LDSM4(ah[mt], sptr(sAh[st]) + off);
            LDSM4(al[mt], sptr(sAl[st]) + off);
        }
        #pragma unroll
        for (int nt = 0; nt < 4; ++nt) {
            int k = lrow;
            int n = wn + nt * 8;
            uint32_t off = k * 256 + (((n >> 3) ^ (k & 7)) << 4);
            LDSMT2(bh[nt], sptr(sBh[st]) + off);
            LDSMT2(bl[nt], sptr(sBl[st]) + off);
        }
        #pragma unroll
        for (int mt = 0; mt < 4; ++mt)
            #pragma unroll
            for (int nt = 0; nt < 4; ++nt) {
                MMA16816(acc[mt][nt], ah[mt], bh[nt]);
                MMA16816(acc[mt][nt], ah[mt], bl[nt]);
                MMA16816(acc[mt][nt], al[mt], bh[nt]);
            }
        __syncthreads();
    }

    #pragma unroll
    for (int nt = 0; nt < 4; ++nt) {
        int cbase = n0 + wn + nt * 8 + 2 * (lane & 3);
        float2 bv = make_float2(0.f, 0.f);
        if (cbase + 1 < VOCAB) bv = *reinterpret_cast<const float2*>(bias + cbase);
        #pragma unroll
        for (int mt = 0; mt < 4; ++mt) {
            int r0 = m0 + wm + mt * 16 + (lane >> 2);
            if (cbase + 1 < VOCAB) {
                float2 v0 = make_float2(acc[mt][nt][0] + bv.x, acc[mt][nt][1] + bv.y);
                float2 v1 = make_float2(acc[mt][nt][2] + bv.x, acc[mt][nt][3] + bv.y);
                *reinterpret_cast<float2*>(C + (size_t)r0 * VOCAB + cbase) = v0;
                *reinterpret_cast<float2*>(C + (size_t)(r0 + 8) * VOCAB + cbase) = v1;
            }
        }
    }
}

// ================= launch =================
extern "C" void kernel_launch(void* const* d_in, const int* in_sizes, int n_in,
                              void* d_out, int out_size) {
    const int*   X   = (const int*)  d_in[0];
    const float* H0  = (const float*)d_in[1];
    const float* Wxz = (const float*)d_in[2];
    const float* Whz = (const float*)d_in[3];
    const float* bz  = (const float*)d_in[4];
    const float* Wxr = (const float*)d_in[5];
    const float* Whr = (const float*)d_in[6];
    const float* br  = (const float*)d_in[7];
    const float* Wxh = (const float*)d_in[8];
    const float* Whh = (const float*)d_in[9];
    const float* bh  = (const float*)d_in[10];
    const float* Whq = (const float*)d_in[11];
    const float* bq  = (const float*)d_in[12];

    float* out  = (float*)d_out;
    float* outF = out + (out_size - BATCH * HID);

    static bool attr_set = false;
    if (!attr_set) {
        cudaFuncSetAttribute(rnn_kernel, cudaFuncAttributeMaxDynamicSharedMemorySize,
                             (int)sizeof(RSmem));
        attr_set = true;
    }

    convB_kernel<<<(HID * VOCAB + 255) / 256, 256>>>(Whq);
    rnn_kernel<<<(BATCH / BPC) * CLUSTER, RTH, sizeof(RSmem)>>>(
        X, H0, Wxz, Whz, bz, Wxr, Whr, br, Wxh, Whh, bh, outF);
    out_gemm<<<dim3((VOCAB + GBN - 1) / GBN, (STEPS * BATCH) / GBM), GTHREADS>>>(bq, out);
}